// round 13
// baseline (speedup 1.0000x reference)
#include <cuda_runtime.h>
#include <stdint.h>
#include <math.h>

// ============================================================================
// L1Wav: 3D db4 (F=8) 5-level wavelet soft-threshold prox, 256^3 complex64 in
// (split re/im), output = real-part float32 (confirmed R10).
// R13: pair the coalesced ii dimension as well (2x2 tile per thread) with
// aligned float4 loads/stores wherever INNER is even; float4 tap loads in
// k_fwd_fin when N is even. Odd-INNER small kernels keep the R12 path.
// ============================================================================

#define THRESH 0.001f

// ---- g_mem layout (float2 units), all even, all < 2^31 ----
#define OFF_T0   0
#define OFF_T1   17170432
#define OFF_APX0 34743296
#define OFF_APX1 37043264
#define OFF_DET  39343232
#define N_MEM    57857280LL

// det sub-offsets per level (7 bands of L^3 each)
#define D1 0
#define D2 15736637
#define D3 18036200
#define D4 18420304
#define D5 18494840

__device__ __align__(16) float2 g_mem[N_MEM];

__constant__ float c_dec_lo[8] = {
  -0.010597401784997278f,  0.032883011666982945f,  0.030841381835986965f, -0.18703481171888114f,
  -0.02798376941698385f,   0.6308807679295904f,    0.7148465705525415f,    0.23037781330885523f };
__constant__ float c_dec_hi[8] = {
  -0.23037781330885523f,   0.7148465705525415f,   -0.6308807679295904f,   -0.02798376941698385f,
   0.18703481171888114f,   0.030841381835986965f, -0.032883011666982945f, -0.010597401784997278f };
__constant__ float c_rec_lo[8] = {
   0.23037781330885523f,   0.7148465705525415f,    0.6308807679295904f,   -0.02798376941698385f,
  -0.18703481171888114f,   0.030841381835986965f,  0.032883011666982945f, -0.010597401784997278f };
__constant__ float c_rec_hi[8] = {
  -0.010597401784997278f, -0.032883011666982945f,  0.030841381835986965f,  0.18703481171888114f,
  -0.02798376941698385f,  -0.6308807679295904f,    0.7148465705525415f,   -0.23037781330885523f };

__device__ __forceinline__ float2 softc(float2 v) {
    float mag = sqrtf(v.x * v.x + v.y * v.y);
    float s = (mag > THRESH) ? (mag - THRESH) / mag : 0.0f;
    return make_float2(v.x * s, v.y * s);
}
__device__ __forceinline__ float4 f4fma(float c, float4 v, float4 a) {
    a.x += c * v.x; a.y += c * v.y; a.z += c * v.z; a.w += c * v.w; return a;
}

// ============================================================================
// Level-1 axis-0 forward with fused roll: x -> T0 [2, 131, 65536].
// Pairs l (l0, l0+1) AND ii (j2, j2+1).
// ============================================================================
__global__ __launch_bounds__(256) void k_fromx(const float* __restrict__ xr,
                                               const float* __restrict__ xi, int shift)
{
    const int inner = 65536, L = 131;
    const int total = 66 * 32768;
    int tid = blockIdx.x * 256 + threadIdx.x;
    if (tid >= total) return;
    int ih = tid & 32767;
    int lh = tid >> 15;
    int l0 = 2 * lh;
    int ii = 2 * ih;
    int j1 = ii >> 8, j2 = ii & 255;
    int o1 = (j1 - shift) & 255;
    int o2 = (j2 - shift) & 255;
    int d1 = (o2 == 255) ? -255 : 1;
    int base = (o1 << 8) + o2;
    float4 alo0 = {0,0,0,0}, ahi0 = {0,0,0,0}, alo1 = {0,0,0,0}, ahi1 = {0,0,0,0};
    int kbase = 4 * lh - 6;
#pragma unroll
    for (int s = 0; s < 10; s++) {
        int k = kbase + s;
        if ((unsigned)k < 256u) {
            int idx = (((k - shift) & 255) << 16) + base;
            float4 v = make_float4(xr[idx], xi[idx], xr[idx + d1], xi[idx + d1]);
            if (s < 8)  { alo0 = f4fma(c_dec_lo[7 - s], v, alo0); ahi0 = f4fma(c_dec_hi[7 - s], v, ahi0); }
            if (s >= 2) { alo1 = f4fma(c_dec_lo[9 - s], v, alo1); ahi1 = f4fma(c_dec_hi[9 - s], v, ahi1); }
        }
    }
    const int band = L * inner;
    float2* dst = g_mem + OFF_T0 + l0 * inner + ii;
    *reinterpret_cast<float4*>(dst)        = alo0;
    *reinterpret_cast<float4*>(dst + band) = ahi0;
    if (l0 + 1 < L) {
        *reinterpret_cast<float4*>(dst + inner)        = alo1;
        *reinterpret_cast<float4*>(dst + band + inner) = ahi1;
    }
}

// ============================================================================
// Forward DWT along middle axis, pairs l; pairs ii too when INNER even.
// in [NBv, OUTER, N, INNER] -> out [2*NBv, OUTER, L, INNER].
// ============================================================================
template<int NBv, int OUTER, int N, int INNER, int L>
__global__ __launch_bounds__(256) void k_fwd_mid(int in_off, int out_off)
{
    constexpr int LH = (L + 1) / 2;
    constexpr bool P = (INNER % 2 == 0);
    constexpr int IH = P ? INNER / 2 : INNER;
    constexpr int TOTAL = NBv * OUTER * LH * IH;
    constexpr int BANDSZ = OUTER * L * INNER;
    int tid = blockIdx.x * 256 + threadIdx.x;
    if (tid >= TOTAL) return;
    int ih = tid % IH;  int t = tid / IH;
    int lh = t % LH;    t /= LH;
    int o  = t % OUTER;
    int b  = t / OUTER;
    int l0 = 2 * lh;
    int ii = P ? 2 * ih : ih;
    const float2* __restrict__ src = g_mem + in_off + (b * OUTER + o) * N * INNER + ii;
    float2* __restrict__ dst = g_mem + out_off + (2 * b * OUTER + o) * L * INNER
                               + l0 * INNER + ii;
    int kbase = 2 * l0 - 6;
    if constexpr (P) {
        float4 alo0 = {0,0,0,0}, ahi0 = {0,0,0,0}, alo1 = {0,0,0,0}, ahi1 = {0,0,0,0};
#pragma unroll
        for (int s = 0; s < 10; s++) {
            int k = kbase + s;
            if ((unsigned)k < (unsigned)N) {
                float4 v = *reinterpret_cast<const float4*>(src + k * INNER);
                if (s < 8)  { alo0 = f4fma(c_dec_lo[7 - s], v, alo0); ahi0 = f4fma(c_dec_hi[7 - s], v, ahi0); }
                if (s >= 2) { alo1 = f4fma(c_dec_lo[9 - s], v, alo1); ahi1 = f4fma(c_dec_hi[9 - s], v, ahi1); }
            }
        }
        *reinterpret_cast<float4*>(dst)          = alo0;
        *reinterpret_cast<float4*>(dst + BANDSZ) = ahi0;
        if (l0 + 1 < L) {
            *reinterpret_cast<float4*>(dst + INNER)          = alo1;
            *reinterpret_cast<float4*>(dst + BANDSZ + INNER) = ahi1;
        }
    } else {
        float2 v[10];
#pragma unroll
        for (int s = 0; s < 10; s++) {
            int k = kbase + s;
            v[s] = ((unsigned)k < (unsigned)N) ? src[k * INNER] : make_float2(0.f, 0.f);
        }
        float lox0=0,loy0=0,hix0=0,hiy0=0, lox1=0,loy1=0,hix1=0,hiy1=0;
#pragma unroll
        for (int s = 0; s < 8; s++) {
            float cl = c_dec_lo[7 - s], ch = c_dec_hi[7 - s];
            lox0 += cl * v[s].x;     loy0 += cl * v[s].y;
            hix0 += ch * v[s].x;     hiy0 += ch * v[s].y;
            lox1 += cl * v[s + 2].x; loy1 += cl * v[s + 2].y;
            hix1 += ch * v[s + 2].x; hiy1 += ch * v[s + 2].y;
        }
        dst[0]      = make_float2(lox0, loy0);
        dst[BANDSZ] = make_float2(hix0, hiy0);
        if (l0 + 1 < L) {
            dst[INNER]          = make_float2(lox1, loy1);
            dst[BANDSZ + INNER] = make_float2(hix1, hiy1);
        }
    }
}

// ============================================================================
// Final (axis-2) forward, pairs l: T1 [4, L, L, N] -> 8 bands (L,L,L).
// When N even: taps loaded as 5 aligned float4s with per-half masking
// (out-of-row reads land inside g_mem and are masked out).
// ============================================================================
template<int L, int N>
__global__ __launch_bounds__(256) void k_fwd_fin(int apx_off, int det_off, int thresh_aaa)
{
    constexpr int LH = (L + 1) / 2;
    constexpr int OUTER = L * L;
    constexpr int TOTAL = 4 * OUTER * LH;
    constexpr int L3 = OUTER * L;
    int tid = blockIdx.x * 256 + threadIdx.x;
    if (tid >= TOTAL) return;
    int lh = tid % LH;  int t = tid / LH;
    int o = t % OUTER;
    int b = t / OUTER;
    int l0 = 2 * lh;
    const float2* __restrict__ src = g_mem + OFF_T1 + (b * OUTER + o) * N;
    float2 v[10];
    int kbase = 2 * l0 - 6;
    if constexpr (N % 2 == 0) {
#pragma unroll
        for (int s2 = 0; s2 < 5; s2++) {
            int k = kbase + 2 * s2;
            float4 w = *reinterpret_cast<const float4*>(src + k);
            v[2*s2]   = ((unsigned)k       < (unsigned)N) ? make_float2(w.x, w.y) : make_float2(0.f, 0.f);
            v[2*s2+1] = ((unsigned)(k + 1) < (unsigned)N) ? make_float2(w.z, w.w) : make_float2(0.f, 0.f);
        }
    } else {
#pragma unroll
        for (int s = 0; s < 10; s++) {
            int k = kbase + s;
            v[s] = ((unsigned)k < (unsigned)N) ? src[k] : make_float2(0.f, 0.f);
        }
    }
    float lox0=0,loy0=0,hix0=0,hiy0=0, lox1=0,loy1=0,hix1=0,hiy1=0;
#pragma unroll
    for (int s = 0; s < 8; s++) {
        float cl = c_dec_lo[7 - s], ch = c_dec_hi[7 - s];
        lox0 += cl * v[s].x;     loy0 += cl * v[s].y;
        hix0 += ch * v[s].x;     hiy0 += ch * v[s].y;
        lox1 += cl * v[s + 2].x; loy1 += cl * v[s + 2].y;
        hix1 += ch * v[s + 2].x; hiy1 += ch * v[s + 2].y;
    }
    int opos = o * L + l0;
    bool has1 = (l0 + 1 < L);
    g_mem[det_off + 2 * b * L3 + opos] = softc(make_float2(hix0, hiy0));
    if (has1) g_mem[det_off + 2 * b * L3 + opos + 1] = softc(make_float2(hix1, hiy1));
    float2 lo0 = make_float2(lox0, loy0);
    float2 lo1 = make_float2(lox1, loy1);
    if (b == 0) {
        g_mem[apx_off + opos] = thresh_aaa ? softc(lo0) : lo0;
        if (has1) g_mem[apx_off + opos + 1] = thresh_aaa ? softc(lo1) : lo1;
    } else {
        g_mem[det_off + (2 * b - 1) * L3 + opos] = softc(lo0);
        if (has1) g_mem[det_off + (2 * b - 1) * L3 + opos + 1] = softc(lo1);
    }
}

// ============================================================================
// Inverse.  Outputs (2h, 2h+1) share identical tap pairs m = h..h+3.
// ============================================================================

// Axis-2 inverse: 8 bands -> T1 [4, L, L, OLEN]. Contiguous pair = one float4.
template<int L, int OLEN, int APN>
__global__ __launch_bounds__(256) void k_inv2(int apx_off, int det_off)
{
    constexpr int QH = OLEN / 2;
    constexpr int L2 = L * L;
    constexpr int L3 = L2 * L;
    constexpr int TOTAL = 4 * L2 * QH;
    int tid = blockIdx.x * 256 + threadIdx.x;
    if (tid >= TOTAL) return;
    int qh = tid % QH;  int t = tid / QH;
    int ij = t % L2;
    int p  = t / L2;
    int i = ij / L, j = ij % L;
    const float2* __restrict__ ca = (p == 0)
        ? (g_mem + apx_off + (i * APN + j) * APN)
        : (g_mem + det_off + (2 * p - 1) * L3 + ij * L);
    const float2* __restrict__ cd = g_mem + det_off + 2 * p * L3 + ij * L;
    float ax0=0,ay0=0,ax1=0,ay1=0;
#pragma unroll
    for (int s = 0; s < 4; s++) {
        int m = qh + s;
        if (m < L) {
            float2 va = ca[m], vd = cd[m];
            float e_l = c_rec_lo[6 - 2 * s], e_h = c_rec_hi[6 - 2 * s];
            float o_l = c_rec_lo[7 - 2 * s], o_h = c_rec_hi[7 - 2 * s];
            ax0 += e_l * va.x + e_h * vd.x;  ay0 += e_l * va.y + e_h * vd.y;
            ax1 += o_l * va.x + o_h * vd.x;  ay1 += o_l * va.y + o_h * vd.y;
        }
    }
    float4* dst = reinterpret_cast<float4*>(g_mem + OFF_T1 + (p * L2 + ij) * OLEN + 2 * qh);
    *dst = make_float4(ax0, ay0, ax1, ay1);
}

// Inverse along middle axis, pairs q; pairs ii too when INNER even.
template<int NP, int OUTER, int LM, int INNER, int OLEN>
__global__ __launch_bounds__(256) void k_inv_mid(int in_off, int out_off)
{
    constexpr int QH = OLEN / 2;
    constexpr bool P = (INNER % 2 == 0);
    constexpr int IH = P ? INNER / 2 : INNER;
    constexpr int TOTAL = NP * OUTER * QH * IH;
    constexpr int BANDSZ = OUTER * LM * INNER;
    int tid = blockIdx.x * 256 + threadIdx.x;
    if (tid >= TOTAL) return;
    int ih = tid % IH;  int t = tid / IH;
    int qh = t % QH;    t /= QH;
    int o  = t % OUTER;
    int p  = t / OUTER;
    int ii = P ? 2 * ih : ih;
    const float2* __restrict__ ca = g_mem + in_off + 2 * p * BANDSZ + o * LM * INNER + ii;
    const float2* __restrict__ cd = ca + BANDSZ;
    float2* __restrict__ dst = g_mem + out_off + (p * OUTER + o) * OLEN * INNER
                               + 2 * qh * INNER + ii;
    if constexpr (P) {
        float4 a0 = {0,0,0,0}, a1 = {0,0,0,0};
#pragma unroll
        for (int s = 0; s < 4; s++) {
            int m = qh + s;
            if (m < LM) {
                float4 va = *reinterpret_cast<const float4*>(ca + m * INNER);
                float4 vd = *reinterpret_cast<const float4*>(cd + m * INNER);
                a0 = f4fma(c_rec_lo[6 - 2 * s], va, a0);
                a0 = f4fma(c_rec_hi[6 - 2 * s], vd, a0);
                a1 = f4fma(c_rec_lo[7 - 2 * s], va, a1);
                a1 = f4fma(c_rec_hi[7 - 2 * s], vd, a1);
            }
        }
        *reinterpret_cast<float4*>(dst)         = a0;
        *reinterpret_cast<float4*>(dst + INNER) = a1;
    } else {
        float ax0=0,ay0=0,ax1=0,ay1=0;
#pragma unroll
        for (int s = 0; s < 4; s++) {
            int m = qh + s;
            if (m < LM) {
                float2 va = ca[m * INNER], vd = cd[m * INNER];
                float e_l = c_rec_lo[6 - 2 * s], e_h = c_rec_hi[6 - 2 * s];
                float o_l = c_rec_lo[7 - 2 * s], o_h = c_rec_hi[7 - 2 * s];
                ax0 += e_l * va.x + e_h * vd.x;  ay0 += e_l * va.y + e_h * vd.y;
                ax1 += o_l * va.x + o_h * vd.x;  ay1 += o_l * va.y + o_h * vd.y;
            }
        }
        dst[0]     = make_float2(ax0, ay0);
        dst[INNER] = make_float2(ax1, ay1);
    }
}

// Level-1 axis-0 inverse with fused un-roll, pairs q and ii; real-part output.
__global__ __launch_bounds__(256) void k_out(float* __restrict__ outf, int out_size, int shift)
{
    const int L = 131, inner = 65536;
    const int total = 128 * 32768;
    int tid = blockIdx.x * 256 + threadIdx.x;
    if (tid >= total) return;
    int ih = tid & 32767;
    int qh = tid >> 15;
    int ii = 2 * ih;
    const float2* __restrict__ ca = g_mem + OFF_T0 + ii;
    const float2* __restrict__ cd = g_mem + OFF_T0 + L * inner + ii;
    float4 a0 = {0,0,0,0}, a1 = {0,0,0,0};
#pragma unroll
    for (int s = 0; s < 4; s++) {
        int m = qh + s;
        if (m < L) {
            float4 va = *reinterpret_cast<const float4*>(ca + m * inner);
            float4 vd = *reinterpret_cast<const float4*>(cd + m * inner);
            a0 = f4fma(c_rec_lo[6 - 2 * s], va, a0);
            a0 = f4fma(c_rec_hi[6 - 2 * s], vd, a0);
            a1 = f4fma(c_rec_lo[7 - 2 * s], va, a1);
            a1 = f4fma(c_rec_hi[7 - 2 * s], vd, a1);
        }
    }
    int j1 = ii >> 8, j2 = ii & 255;
    int o1 = (j1 - shift) & 255;
    int o2 = (j2 - shift) & 255;
    int d1 = (o2 == 255) ? -255 : 1;
    int oi0 = (2 * qh - shift) & 255;
    int oi1 = (2 * qh + 1 - shift) & 255;
    int obase = (o1 << 8) + o2;
    int x0 = (oi0 << 16) + obase;
    int x1 = (oi1 << 16) + obase;
    if (out_size >= 33554432) {
        long long f0 = 2LL * x0, f0b = 2LL * (x0 + d1);
        long long f1 = 2LL * x1, f1b = 2LL * (x1 + d1);
        if (f0  + 1 < (long long)out_size) { outf[f0]  = a0.x; outf[f0 + 1]  = a0.y; }
        if (f0b + 1 < (long long)out_size) { outf[f0b] = a0.z; outf[f0b + 1] = a0.w; }
        if (f1  + 1 < (long long)out_size) { outf[f1]  = a1.x; outf[f1 + 1]  = a1.y; }
        if (f1b + 1 < (long long)out_size) { outf[f1b] = a1.z; outf[f1b + 1] = a1.w; }
    } else {
        if (x0      < out_size) outf[x0]      = a0.x;
        if (x0 + d1 < out_size) outf[x0 + d1] = a0.z;
        if (x1      < out_size) outf[x1]      = a1.x;
        if (x1 + d1 < out_size) outf[x1 + d1] = a1.z;
    }
}

// ============================================================================
// Host: numpy default_rng(1000).uniform(-3,3) -> shift
// ============================================================================
static int compute_shift(void)
{
    const uint32_t INIT_A = 0x43b0d7e5u, MULT_A = 0x931e8875u;
    const uint32_t INIT_B = 0x8b51f9ddu, MULT_B = 0x58f38dedu;
    const uint32_t MIX_L  = 0xca01f9ddu, MIX_R  = 0x4973f715u;
    uint32_t pool[4];
    uint32_t hc = INIT_A;
    for (int i = 0; i < 4; i++) {
        uint32_t v = (i < 1) ? 1000u : 0u;
        v ^= hc; hc *= MULT_A; v *= hc; v ^= v >> 16;
        pool[i] = v;
    }
    for (int s = 0; s < 4; s++)
        for (int d = 0; d < 4; d++)
            if (s != d) {
                uint32_t v = pool[s];
                v ^= hc; hc *= MULT_A; v *= hc; v ^= v >> 16;
                uint32_t r = (pool[d] * MIX_L) ^ (v * MIX_R);
                r ^= r >> 16;
                pool[d] = r;
            }
    uint32_t o32[8];
    uint32_t hb = INIT_B;
    for (int i = 0; i < 8; i++) {
        uint32_t v = pool[i & 3];
        v ^= hb; hb *= MULT_B; v *= hb; v ^= v >> 16;
        o32[i] = v;
    }
    uint64_t u64[4];
    for (int k = 0; k < 4; k++)
        u64[k] = (uint64_t)o32[2 * k] | ((uint64_t)o32[2 * k + 1] << 32);

    typedef unsigned __int128 u128;
    const u128 MUL = ((u128)2549297995355413924ULL << 64) | 4865540595714422341ULL;
    u128 seed = ((u128)u64[0] << 64) | u64[1];
    u128 iseq = ((u128)u64[2] << 64) | u64[3];
    u128 inc = (iseq << 1) | 1;
    u128 state = 0;
    state = state * MUL + inc;           // srandom step 1
    state += seed;
    state = state * MUL + inc;           // srandom step 2
    state = state * MUL + inc;           // next64 (first draw)
    uint64_t hi = (uint64_t)(state >> 64), lo = (uint64_t)state;
    uint64_t val = hi ^ lo;
    unsigned rot = (unsigned)(hi >> 58);
    uint64_t out64 = (val >> rot) | (val << ((64u - rot) & 63u));
    double d = (double)(out64 >> 11) * (1.0 / 9007199254740992.0);
    double u = -3.0 + 6.0 * d;
    return (int)rint(u);
}

// ============================================================================
// kernel_launch
// ============================================================================
extern "C" void kernel_launch(void* const* d_in, const int* in_sizes, int n_in,
                              void* d_out, int out_size)
{
    // The two largest inputs are (x_real, x_imag), order-preserving.
    int i0 = -1, i1 = -1;
    for (int i = 0; i < n_in; i++) {
        long long s  = (long long)in_sizes[i];
        long long s0 = (i0 >= 0) ? (long long)in_sizes[i0] : -1;
        long long s1 = (i1 >= 0) ? (long long)in_sizes[i1] : -1;
        if (s > s0) { i1 = i0; i0 = i; }
        else if (s > s1) { i1 = i; }
    }
    if (i0 < 0) i0 = 0;
    if (i1 < 0) i1 = (n_in > 1) ? 1 : 0;
    int a = (i0 < i1) ? i0 : i1;
    int b = (i0 < i1) ? i1 : i0;
    const float* xr = (const float*)d_in[a];
    const float* xi = (const float*)d_in[b];
    float* outf = (float*)d_out;

    int shift = compute_shift();

#define NB(total) ((unsigned)(((total) + 255) / 256))
#define LHV(L) (((L) + 1) / 2)
#define IHV(I) (((I) % 2 == 0) ? (I) / 2 : (I))

    // ================= forward =================
    k_fromx<<<NB(66 * 32768), 256>>>(xr, xi, shift);
    k_fwd_mid<2, 131, 256, 256, 131><<<NB(2 * 131 * LHV(131) * IHV(256)), 256>>>(OFF_T0, OFF_T1);
    k_fwd_fin<131, 256><<<NB(4 * 131 * 131 * LHV(131)), 256>>>(OFF_APX0, OFF_DET + D1, 0);

    k_fwd_mid<1, 1, 131, 17161, 69><<<NB(LHV(69) * IHV(17161)), 256>>>(OFF_APX0, OFF_T0);
    k_fwd_mid<2, 69, 131, 131, 69><<<NB(2 * 69 * LHV(69) * IHV(131)), 256>>>(OFF_T0, OFF_T1);
    k_fwd_fin<69, 131><<<NB(4 * 69 * 69 * LHV(69)), 256>>>(OFF_APX1, OFF_DET + D2, 0);

    k_fwd_mid<1, 1, 69, 4761, 38><<<NB(LHV(38) * IHV(4761)), 256>>>(OFF_APX1, OFF_T0);
    k_fwd_mid<2, 38, 69, 69, 38><<<NB(2 * 38 * LHV(38) * IHV(69)), 256>>>(OFF_T0, OFF_T1);
    k_fwd_fin<38, 69><<<NB(4 * 38 * 38 * LHV(38)), 256>>>(OFF_APX0, OFF_DET + D3, 0);

    k_fwd_mid<1, 1, 38, 1444, 22><<<NB(LHV(22) * IHV(1444)), 256>>>(OFF_APX0, OFF_T0);
    k_fwd_mid<2, 22, 38, 38, 22><<<NB(2 * 22 * LHV(22) * IHV(38)), 256>>>(OFF_T0, OFF_T1);
    k_fwd_fin<22, 38><<<NB(4 * 22 * 22 * LHV(22)), 256>>>(OFF_APX1, OFF_DET + D4, 0);

    k_fwd_mid<1, 1, 22, 484, 14><<<NB(LHV(14) * IHV(484)), 256>>>(OFF_APX1, OFF_T0);
    k_fwd_mid<2, 14, 22, 22, 14><<<NB(2 * 14 * LHV(14) * IHV(22)), 256>>>(OFF_T0, OFF_T1);
    k_fwd_fin<14, 22><<<NB(4 * 14 * 14 * LHV(14)), 256>>>(OFF_APX0, OFF_DET + D5, 1);

    // ================= inverse =================
    k_inv2<14, 22, 14><<<NB(4 * 14 * 14 * 11), 256>>>(OFF_APX0, OFF_DET + D5);
    k_inv_mid<2, 14, 14, 22, 22><<<NB(2 * 14 * 11 * IHV(22)), 256>>>(OFF_T1, OFF_T0);
    k_inv_mid<1, 1, 14, 484, 22><<<NB(11 * IHV(484)), 256>>>(OFF_T0, OFF_APX1);

    k_inv2<22, 38, 22><<<NB(4 * 22 * 22 * 19), 256>>>(OFF_APX1, OFF_DET + D4);
    k_inv_mid<2, 22, 22, 38, 38><<<NB(2 * 22 * 19 * IHV(38)), 256>>>(OFF_T1, OFF_T0);
    k_inv_mid<1, 1, 22, 1444, 38><<<NB(19 * IHV(1444)), 256>>>(OFF_T0, OFF_APX0);

    k_inv2<38, 70, 38><<<NB(4 * 38 * 38 * 35), 256>>>(OFF_APX0, OFF_DET + D3);
    k_inv_mid<2, 38, 38, 70, 70><<<NB(2 * 38 * 35 * IHV(70)), 256>>>(OFF_T1, OFF_T0);
    k_inv_mid<1, 1, 38, 4900, 70><<<NB(35 * IHV(4900)), 256>>>(OFF_T0, OFF_APX1);

    k_inv2<69, 132, 70><<<NB(4 * 69 * 69 * 66), 256>>>(OFF_APX1, OFF_DET + D2);
    k_inv_mid<2, 69, 69, 132, 132><<<NB(2 * 69 * 66 * IHV(132)), 256>>>(OFF_T1, OFF_T0);
    k_inv_mid<1, 1, 69, 17424, 132><<<NB(66 * IHV(17424)), 256>>>(OFF_T0, OFF_APX0);

    k_inv2<131, 256, 132><<<NB(4 * 131 * 131 * 128), 256>>>(OFF_APX0, OFF_DET + D1);
    k_inv_mid<2, 131, 131, 256, 256><<<NB(2 * 131 * 128 * IHV(256)), 256>>>(OFF_T1, OFF_T0);
    k_out<<<NB(128 * 32768), 256>>>(outf, out_size, shift);
#undef IHV
#undef LHV
#undef NB
}